// round 11
// baseline (speedup 1.0000x reference)
#include <cuda_runtime.h>
#include <cfloat>

#define T_DIM 2048
#define R_DIM 256
#define BS_DIM 32
#define IDX(t) ((t) + ((t) >> 5))   // smem skew: 1 pad float per 32
#define CSK 2112                    // skewed column size: 2048 + 64

#define LAG 64                      // w2 group lag behind cdf groups
#define NGROUPS (1024 + LAG)

// 128 MB transposed CDF scratch: [array][bs][r][t]
__device__ float g_cdf[2][BS_DIM][R_DIM][T_DIM];
// per-segment totals (segments of 128 t): [array][bs][r][seg16]
__device__ float g_segtot[2][BS_DIM][R_DIM][16];
// per-K1-block minima (512 entries, fully overwritten each call)
__device__ float g_blockmin[512];
// cdf completion counters: [array][bs][rtile] -> target 2 (two t-halves)
__device__ int g_done[2][BS_DIM][8];

struct SmemU {
    union {
        float tile[8][32][33];       // cdf: 33.8 KB
        float sm[4 * CSK + 32];      // w2: 33.9 KB (+ pad for dead loads)
    };
    float wmin[8];
    float coffs[4][16];
    float cinv[4];
    float csinv[4];
    float warr[8];
};

// ---------------- cdf body: transpose + segment cumsum ----------------
__device__ __forceinline__ void do_cdf(const float* __restrict__ src0, int a, int bs,
                                       int r0, int tb, SmemU* S, int lane, int seg) {
    const float* src = src0 + (size_t)bs * T_DIM * R_DIM + r0 + lane;
    float run = 0.0f;
    const int row = lane >> 3;
    const int c4  = lane & 7;
    float (*tile)[33] = S->tile[seg];

    #pragma unroll 1
    for (int ch = 0; ch < 4; ch++) {
        const int t0 = tb + seg * 128 + ch * 32;
        #pragma unroll
        for (int h = 0; h < 2; h++) {
            float v[16];
            #pragma unroll
            for (int i = 0; i < 16; i++)
                v[i] = src[(size_t)(t0 + h * 16 + i) * R_DIM];
            #pragma unroll
            for (int i = 0; i < 16; i++) {
                run += v[i];
                tile[lane][h * 16 + i] = run;
            }
        }
        __syncwarp();
        #pragma unroll
        for (int rb = 0; rb < 8; rb++) {
            int rr = rb * 4 + row;
            float4 o;
            o.x = tile[rr][c4 * 4 + 0];
            o.y = tile[rr][c4 * 4 + 1];
            o.z = tile[rr][c4 * 4 + 2];
            o.w = tile[rr][c4 * 4 + 3];
            *(float4*)&g_cdf[a][bs][r0 + rr][t0 + c4 * 4] = o;
        }
        __syncwarp();
    }
    g_segtot[a][bs][r0 + lane][(tb >> 7) + seg] = run;
}

// ---------------- w2 body: stage normalized CDFs + merge-path ----------------
__device__ __forceinline__ void do_w2(int bs, int r0, float* __restrict__ out, SmemU* S,
                                      int tid) {
    // global min from g_blockmin (512 entries, L2-resident)
    {
        float m = fminf(g_blockmin[tid], g_blockmin[tid + 256]);
        for (int o = 16; o; o >>= 1) m = fminf(m, __shfl_xor_sync(0xffffffffu, m, o));
        if ((tid & 31) == 0) S->wmin[tid >> 5] = m;
    }
    __syncthreads();
    float mnv = S->wmin[0];
    #pragma unroll
    for (int i = 1; i < 8; i++) mnv = fminf(mnv, S->wmin[i]);
    const float shift = (mnv < 0.0f) ? (-1.1f * mnv) : 0.0f;

    if (tid < 4) {
        int c = tid, aa = c & 1, pp = c >> 1;
        const float* st = g_segtot[aa][bs][r0 + pp];
        float pref[16];
        float runp = 0.0f;
        #pragma unroll
        for (int s = 0; s < 16; s++) { pref[s] = runp; runp += st[s]; }
        float inv = 1.0f / (runp + 2048.0f * shift);
        S->cinv[c] = inv;
        S->csinv[c] = shift * inv;
        #pragma unroll
        for (int s = 0; s < 16; s++) S->coffs[c][s] = pref[s] * inv;
    }
    __syncthreads();

    {
        const int c = tid >> 6;
        const int l64 = tid & 63;
        const int aa = c & 1, pp = c >> 1;
        const float4* srcc = (const float4*)&g_cdf[aa][bs][r0 + pp][0];
        float* dst = S->sm + c * CSK;
        const float inv = S->cinv[c];
        const float si  = S->csinv[c];
        const float si2 = si + si;
        float tf = (float)(l64 * 4);
        #pragma unroll
        for (int it = 0; it < 8; it++) {
            int t4 = it * 64 + l64;
            float4 v = srcc[t4];
            int t = t4 * 4;
            float base = fmaf(tf + 1.0f, si, S->coffs[c][t >> 7]);
            dst[IDX(t + 0)] = fmaf(v.x, inv, base);
            dst[IDX(t + 1)] = fmaf(v.y, inv, base + si);
            dst[IDX(t + 2)] = fmaf(v.z, inv, base + si2);
            dst[IDX(t + 3)] = fmaf(v.w, inv, base + si2 + si);
            tf += 256.0f;
        }
    }
    __syncthreads();

    const int p = tid >> 7;
    const int l = tid & 127;
    const int k0 = l * 32;
    const float* A = S->sm + (p * 2 + 0) * CSK;
    const float* B = S->sm + (p * 2 + 1) * CSK;

    int lo = (k0 > T_DIM) ? (k0 - T_DIM) : 0;
    int hi = (k0 < T_DIM) ? k0 : T_DIM;
    while (lo < hi) {
        int mid = (lo + hi) >> 1;
        if (A[IDX(mid)] <= B[IDX(k0 - 1 - mid)]) lo = mid + 1;
        else hi = mid;
    }
    int i = lo;
    int j = k0 - lo;

    float prevA = i ? A[IDX(i - 1)] : 0.0f;
    float prevB = j ? B[IDX(j - 1)] : 0.0f;
    float prev0 = fmaxf(prevA, prevB);
    float aq = (i < T_DIM) ? A[IDX(i)] : FLT_MAX;
    float bq = (j < T_DIM) ? B[IDX(j)] : FLT_MAX;
    float acc = 0.0f;

    if ((tid & 64) == 0) {
        // LEAN (ranks <= 2047): Abel form + exact per-chunk boundary terms.
        float fd0 = (float)(i - j);
        float fd2 = fd0 + fd0;
        acc = -prev0 * (fd0 * fd0);
        float lastq = prev0;
        #pragma unroll 8
        for (int s = 0; s < 32; s++) {
            bool takeA = (aq <= bq);
            float q = fminf(aq, bq);
            float sd = takeA ? -1.0f : 1.0f;
            float w = fmaf(sd, fd2, -1.0f);
            acc = fmaf(q, w, acc);
            fd2 = fmaf(-2.0f, sd, fd2);
            lastq = q;
            if (takeA) { i++; aq = A[IDX(i)]; }
            else       { j++; bq = B[IDX(j)]; }
        }
        float fdN = fd2 * 0.5f;
        acc = fmaf(lastq, fdN * fdN, acc);
    } else {
        // CLAMPED (ranks >= 2048)
        float prev = prev0;
        #pragma unroll 8
        for (int s = 0; s < 32; s++) {
            bool takeA = (aq <= bq);
            float q = fminf(aq, bq);
            int ic = (i < 2047) ? i : 2047;
            int jc = (j < 2047) ? j : 2047;
            float diff = (float)(ic - jc);
            acc += (q - prev) * (diff * diff);
            prev = q;
            if (takeA) { i++; aq = (i < T_DIM) ? A[IDX(i)] : FLT_MAX; }
            else       { j++; bq = (j < T_DIM) ? B[IDX(j)] : FLT_MAX; }
        }
    }
    acc *= (1.0f / 2048.0f) * (1.0f / 2048.0f);

    for (int o = 16; o; o >>= 1) acc += __shfl_xor_sync(0xffffffffu, acc, o);
    if ((tid & 31) == 0) S->warr[tid >> 5] = acc;
    __syncthreads();
    if (tid == 0) {
        float s = 0.0f;
        #pragma unroll
        for (int i2 = 0; i2 < 8; i2++) s += S->warr[i2];
        atomicAdd(&out[bs >> 3], s);
    }
}

// ---------------- K1: min-only pass (bs-descending) + init ----------------
__global__ void __launch_bounds__(256) min_kernel(const float* __restrict__ x,
                                                  const float* __restrict__ y,
                                                  float* __restrict__ out) {
    __shared__ float wmin[8];
    const int tid = threadIdx.x;
    const int bid = blockIdx.x;
    if (bid == 0) {
        if (tid < 4) out[tid] = 0.0f;
        int* d = &g_done[0][0][0];
        for (int i = tid; i < 2 * BS_DIM * 8; i += 256) d[i] = 0;
    }
    // idx descending so bs0 of both arrays is read LAST (L2-warm for K2's first cdf)
    const int idx = 511 - bid;
    const float* base = (idx & 1) ? y : x;
    const float4* p = (const float4*)base + (size_t)(idx >> 1) * 16384;  // 256 KB chunk
    float mn = FLT_MAX;
    #pragma unroll 8
    for (int k = 0; k < 64; k++) {
        float4 v = p[k * 256 + tid];
        mn = fminf(mn, fminf(fminf(v.x, v.y), fminf(v.z, v.w)));
    }
    for (int o = 16; o; o >>= 1) mn = fminf(mn, __shfl_xor_sync(0xffffffffu, mn, o));
    if ((tid & 31) == 0) wmin[tid >> 5] = mn;
    __syncthreads();
    if (tid == 0) {
        float m = wmin[0];
        #pragma unroll
        for (int i = 1; i < 8; i++) m = fminf(m, wmin[i]);
        g_blockmin[bid] = m;
    }
}

// ---------------- K2: dynamic cdf || w2 pipeline, counter-gated ----------------
// Groups of 5 bids: slot 0 = cdf item g; slots 1-4 = w2 items (g-LAG)*4+(s-1).
// w2 for bs b only depends on cdf items 32b..32b+31 (groups 32b..32b+31), and is
// placed at groups >= 32b+LAG > 32b+31  =>  all deps have strictly smaller bid
// => dispatch-order safe (no deadlock), spins nearly always pre-satisfied.
__global__ void __launch_bounds__(256, 5) pipe_kernel(const float* __restrict__ x,
                                                      const float* __restrict__ y,
                                                      float* __restrict__ out) {
    __shared__ SmemU S;
    const int tid = threadIdx.x;
    const int bid = blockIdx.x;
    const int g = bid / 5;
    const int s = bid % 5;

    if (s == 0) {
        if (g >= 1024) return;
        // cdf item g, bs-major order
        const int bs  = g >> 5;
        const int rem = g & 31;
        const int a   = rem & 1;
        const int rt  = (rem >> 1) & 7;
        const int th  = rem >> 4;
        do_cdf(a ? y : x, a, bs, rt * 32, th * 1024, &S, tid & 31, tid >> 5);
        __threadfence();
        __syncthreads();
        if (tid == 0) atomicAdd(&g_done[a][bs][rt], 1);
    } else {
        const int v = (g - LAG) * 4 + (s - 1);
        if (v < 0 || v >= 4096) return;
        const int bs = v >> 7;
        const int r0 = (v & 127) * 2;
        const int rt = r0 >> 5;
        if (tid == 0) {
            volatile int* d0 = &g_done[0][bs][rt];
            volatile int* d1 = &g_done[1][bs][rt];
            while (*d0 < 2) __nanosleep(32);
            while (*d1 < 2) __nanosleep(32);
            __threadfence();
        }
        __syncthreads();
        do_w2(bs, r0, out, &S, tid);
    }
}

extern "C" void kernel_launch(void* const* d_in, const int* in_sizes, int n_in,
                              void* d_out, int out_size) {
    const float* x = (const float*)d_in[0];
    const float* y = (const float*)d_in[1];
    float* out = (float*)d_out;

    min_kernel<<<512, 256>>>(x, y, out);
    pipe_kernel<<<NGROUPS * 5, 256>>>(x, y, out);
}